// round 2
// baseline (speedup 1.0000x reference)
#include <cuda_runtime.h>
#include <math.h>

#define DEVINL __device__ __forceinline__

namespace {

constexpr int Bn   = 32;   // batch
constexpr int Tn   = 256;  // timesteps
constexpr int Nn   = 128;  // nodes
constexpr int DINn = 16;   // input features
constexpr int Un   = 64;   // hidden units
constexpr int Cn   = 4;    // classes
constexpr int CB   = 16;   // channel block
constexpr int NTHREADS = 512;
constexpr int PST = 129;   // padded support row stride (bank-conflict free)

struct Smem {
  float P[Nn * PST];      // support, padded rows
  float h0[Nn * Un];      // layer-0 hidden
  float h1[Nn * Un];      // layer-1 hidden
  float xbuf[Nn * DINn];  // current input frame
  float zb0[Nn * CB];     // diffusion block buffers
  float zb1[Nn * CB];
  float zb2[Nn * CB];
  float ubuf[Nn * Un];    // update gate
  float rh[Nn * Un];      // reset gate * h
};

// zb1[n][c] = sum_k P[n][k] * zb0[k][c]   (per thread: 1 node x 4 channels)
DEVINL void diffuse1(Smem& S, int tid) {
  const int c4 = (tid & 3) * 4;
  const int n  = tid >> 2;
  const float* Pr = &S.P[n * PST];
  float a0 = 0.f, a1 = 0.f, a2 = 0.f, a3 = 0.f;
#pragma unroll 8
  for (int k = 0; k < Nn; ++k) {
    const float p = Pr[k];
    const float4 z = *reinterpret_cast<const float4*>(&S.zb0[k * CB + c4]);
    a0 = fmaf(p, z.x, a0); a1 = fmaf(p, z.y, a1);
    a2 = fmaf(p, z.z, a2); a3 = fmaf(p, z.w, a3);
  }
  *reinterpret_cast<float4*>(&S.zb1[n * CB + c4]) = make_float4(a0, a1, a2, a3);
}

// zb2 = 2 * P * zb1 - zb0
DEVINL void diffuse2(Smem& S, int tid) {
  const int c4 = (tid & 3) * 4;
  const int n  = tid >> 2;
  const float* Pr = &S.P[n * PST];
  float a0 = 0.f, a1 = 0.f, a2 = 0.f, a3 = 0.f;
#pragma unroll 8
  for (int k = 0; k < Nn; ++k) {
    const float p = Pr[k];
    const float4 z = *reinterpret_cast<const float4*>(&S.zb1[k * CB + c4]);
    a0 = fmaf(p, z.x, a0); a1 = fmaf(p, z.y, a1);
    a2 = fmaf(p, z.z, a2); a3 = fmaf(p, z.w, a3);
  }
  const float4 z0 = *reinterpret_cast<const float4*>(&S.zb0[n * CB + c4]);
  *reinterpret_cast<float4*>(&S.zb2[n * CB + c4]) =
      make_float4(2.f * a0 - z0.x, 2.f * a1 - z0.y,
                  2.f * a2 - z0.z, 2.f * a3 - z0.w);
}

// Accumulate one channel block of the projection:
// acc[n][o] += sum_{cc,m} z_m[n][cb+cc] * W[(cb+cc)*3+m][o]
template <int OB>
DEVINL void accum_block(Smem& S, int tid, const float* __restrict__ W, int cb,
                        float acc[4][OB]) {
  constexpr int COUT = OB * 16;
  const int og = tid & 15;
  const int rg = tid >> 4;
#pragma unroll 2
  for (int cc = 0; cc < CB; ++cc) {
    const int c = cb + cc;
    const float* w0 = W + (size_t)(c * 3) * COUT + og * OB;
    float z0[4], z1[4], z2[4];
#pragma unroll
    for (int i = 0; i < 4; ++i) {
      const int n = rg * 4 + i;
      z0[i] = S.zb0[n * CB + cc];
      z1[i] = S.zb1[n * CB + cc];
      z2[i] = S.zb2[n * CB + cc];
    }
#pragma unroll
    for (int j = 0; j < OB; ++j) {
      const float wa = w0[j];
      const float wb = w0[COUT + j];
      const float wc = w0[2 * COUT + j];
#pragma unroll
      for (int i = 0; i < 4; ++i)
        acc[i][j] = fmaf(z0[i], wa, fmaf(z1[i], wb, fmaf(z2[i], wc, acc[i][j])));
    }
  }
}

// Full graph-conv + projection: y = [z, Pz, 2P^2 z - z] @ W  (bias added in epilogue)
// z = concat(x-part (XCH ch), h-part (64 ch)); all sources live in SMEM.
template <int XCH, int OB>
DEVINL void gconv(Smem& S, int tid, const float* xs, int xstride,
                  const float* hs, const float* __restrict__ W, float acc[4][OB]) {
  constexpr int CIN = XCH + Un;
  const int ns = tid >> 2;
  const int c4 = (tid & 3) * 4;
  for (int cb = 0; cb < CIN; cb += CB) {
    const float* src;
    int stride, col0;
    if (cb < XCH) { src = xs; stride = xstride; col0 = cb; }
    else          { src = hs; stride = Un;      col0 = cb - XCH; }
    const float4 v =
        *reinterpret_cast<const float4*>(src + ns * stride + col0 + c4);
    *reinterpret_cast<float4*>(&S.zb0[ns * CB + c4]) = v;
    __syncthreads();
    diffuse1(S, tid);
    __syncthreads();
    diffuse2(S, tid);
    __syncthreads();
    accum_block<OB>(S, tid, W, cb, acc);
    __syncthreads();
  }
}

// One DCGRU cell: h <- u*h + (1-u)*tanh(gconv([x, r*h]) Wc + bc),
//   [r|u] = sigmoid(gconv([x, h]) Wg + bg)
template <int XCH>
DEVINL void cell(Smem& S, int tid, const float* xs, int xstride, float* h,
                 const float* __restrict__ Wg, const float* __restrict__ bg,
                 const float* __restrict__ Wc, const float* __restrict__ bc) {
  const int og = tid & 15;
  const int rg = tid >> 4;
  // ---- gate ----
  {
    float acc[4][8];
#pragma unroll
    for (int i = 0; i < 4; ++i)
#pragma unroll
      for (int j = 0; j < 8; ++j) acc[i][j] = 0.f;
    gconv<XCH, 8>(S, tid, xs, xstride, h, Wg, acc);
#pragma unroll
    for (int j = 0; j < 8; ++j) {
      const int o = og * 8 + j;
      const float bias = bg[o];
#pragma unroll
      for (int i = 0; i < 4; ++i) {
        const int n = rg * 4 + i;
        const float v = 1.f / (1.f + __expf(-(acc[i][j] + bias)));
        if (o < Un) S.rh[n * Un + o] = v * h[n * Un + o];       // r * h
        else        S.ubuf[n * Un + (o - Un)] = v;              // u
      }
    }
    __syncthreads();
  }
  // ---- candidate + state update ----
  {
    float acc[4][4];
#pragma unroll
    for (int i = 0; i < 4; ++i)
#pragma unroll
      for (int j = 0; j < 4; ++j) acc[i][j] = 0.f;
    gconv<XCH, 4>(S, tid, xs, xstride, S.rh, Wc, acc);
#pragma unroll
    for (int j = 0; j < 4; ++j) {
      const int o = og * 4 + j;
      const float bias = bc[o];
#pragma unroll
      for (int i = 0; i < 4; ++i) {
        const int n = rg * 4 + i;
        const float cv = tanhf(acc[i][j] + bias);
        const float u = S.ubuf[n * Un + o];
        h[n * Un + o] = u * h[n * Un + o] + (1.f - u) * cv;
      }
    }
    __syncthreads();
  }
}

}  // namespace

__global__ void __launch_bounds__(NTHREADS, 1) dcgru_kernel(
    const float* __restrict__ x_all,   // (B,T,N,DIN)
    const int* __restrict__ seq_len,   // (B)
    const float* __restrict__ support, // (N,N)
    const float* __restrict__ W0g, const float* __restrict__ b0g,
    const float* __restrict__ W0c, const float* __restrict__ b0c,
    const float* __restrict__ W1g, const float* __restrict__ b1g,
    const float* __restrict__ W1c, const float* __restrict__ b1c,
    const float* __restrict__ Wfc, const float* __restrict__ bfc,
    float* __restrict__ out) {        // (B,C)
  extern __shared__ float smraw[];
  Smem& S = *reinterpret_cast<Smem*>(smraw);
  const int b = blockIdx.x;
  const int tid = threadIdx.x;

  // Load support into padded SMEM; zero hidden states.
  for (int i = tid; i < Nn * Nn; i += NTHREADS)
    S.P[(i >> 7) * PST + (i & 127)] = support[i];
  for (int i = tid; i < Nn * Un; i += NTHREADS) {
    S.h0[i] = 0.f;
    S.h1[i] = 0.f;
  }
  __syncthreads();

  const int tlast = seq_len[b] - 1;  // only steps <= tlast affect the output

  for (int t = 0; t <= tlast; ++t) {
    // stage current input frame (2048 floats = 512 float4)
    const float4* xt = reinterpret_cast<const float4*>(
        x_all + ((size_t)b * Tn + t) * (Nn * DINn));
    reinterpret_cast<float4*>(S.xbuf)[tid] = xt[tid];
    __syncthreads();
    cell<DINn>(S, tid, S.xbuf, DINn, S.h0, W0g, b0g, W0c, b0c);
    cell<Un>(S, tid, S.h0, Un, S.h1, W1g, b1g, W1c, b1c);
  }

  // Classifier on h1 at t = tlast: max_n( relu(h1) @ Wfc + bfc )
  {
    const int n = tid >> 2;
    const int c = tid & 3;
    float a = 0.f;
#pragma unroll 8
    for (int u = 0; u < Un; ++u)
      a = fmaf(fmaxf(S.h1[n * Un + u], 0.f), Wfc[u * Cn + c], a);
    S.zb0[n * Cn + c] = a + bfc[c];
    __syncthreads();
    if (tid < Cn) {
      float m = S.zb0[tid];
      for (int n2 = 1; n2 < Nn; ++n2) m = fmaxf(m, S.zb0[n2 * Cn + tid]);
      out[b * Cn + tid] = m;
    }
  }
}

extern "C" void kernel_launch(void* const* d_in, const int* in_sizes, int n_in,
                              void* d_out, int out_size) {
  const float* x   = (const float*)d_in[0];
  const int*   sl  = (const int*)d_in[1];
  const float* sup = (const float*)d_in[2];
  const float* W0g = (const float*)d_in[3];
  const float* b0g = (const float*)d_in[4];
  const float* W0c = (const float*)d_in[5];
  const float* b0c = (const float*)d_in[6];
  const float* W1g = (const float*)d_in[7];
  const float* b1g = (const float*)d_in[8];
  const float* W1c = (const float*)d_in[9];
  const float* b1c = (const float*)d_in[10];
  const float* Wfc = (const float*)d_in[11];
  const float* bfc = (const float*)d_in[12];
  float* out = (float*)d_out;

  const size_t smem = sizeof(Smem);
  cudaFuncSetAttribute(dcgru_kernel,
                       cudaFuncAttributeMaxDynamicSharedMemorySize, (int)smem);
  dcgru_kernel<<<Bn, NTHREADS, smem>>>(x, sl, sup, W0g, b0g, W0c, b0c,
                                       W1g, b1g, W1c, b1c, Wfc, bfc, out);
}